// round 14
// baseline (speedup 1.0000x reference)
#include <cuda_runtime.h>
#include <cuda_fp16.h>
#include <cstdint>

#define HWX   3136
#define WW    56
#define CTOT  256
#define NIMG  64
#define NPIX  (NIMG * HWX)          // 200704
#define NTILE 50176                 // 64 img * 28*28 winograd tiles

// Intermediate y, NHWC fp32: [img*hw][256]
__device__ float g_y[(size_t)NPIX * CTOT];
// Winograd-transformed input V[pos 16][tile][ic 256], fp16
__device__ __half g_V[(size_t)16 * NTILE * 256];
// Winograd-transformed weights, fp16
__device__ __half g_UA[16 * 64 * 64];      // [p][oc][ic]
__device__ __half g_UB[16 * 192 * 192];    // [p][oc][ic]

__device__ __forceinline__ uint32_t smem_u32(const void* p) {
    uint32_t a;
    asm("{ .reg .u64 t; cvta.to.shared.u64 t, %1; cvt.u32.u64 %0, t; }" : "=r"(a) : "l"(p));
    return a;
}

// ---------------------------------------------------------------------------
// Stage 1: temporal DW conv, NCHW fp32 -> NHWC fp32, smem transpose.
// ---------------------------------------------------------------------------
__global__ __launch_bounds__(256) void temporal_nhwc_kernel(
    const float* __restrict__ x,
    const float* __restrict__ w11, const float* __restrict__ w13,
    const float* __restrict__ w15, const float* __restrict__ w17,
    const float* __restrict__ w21, const float* __restrict__ w23,
    const float* __restrict__ w25, const float* __restrict__ w27)
{
    __shared__ float s[32][33];
    const int tx = threadIdx.x, ty = threadIdx.y;
    const int n = blockIdx.z, c0 = blockIdx.y * 32, hw0 = blockIdx.x * 32;

    float v[4][8], o[4][8];
#pragma unroll
    for (int j = 0; j < 4; j++) {
        int c = c0 + ty * 4 + j;
        const float* xb = x + ((size_t)(n * 8) * CTOT + c) * HWX + hw0 + tx;
#pragma unroll
        for (int t = 0; t < 8; t++) v[j][t] = xb[(size_t)t * CTOT * HWX];
    }
#pragma unroll
    for (int j = 0; j < 4; j++) {
        int c = c0 + ty * 4 + j;
        int k, cg; const float* wp;
        if      (c < 16)  { k = 1; wp = w11; cg = c;       }
        else if (c < 32)  { k = 3; wp = w13; cg = c - 16;  }
        else if (c < 48)  { k = 5; wp = w15; cg = c - 32;  }
        else if (c < 64)  { k = 7; wp = w17; cg = c - 48;  }
        else if (c < 112) { k = 1; wp = w21; cg = c - 64;  }
        else if (c < 160) { k = 3; wp = w23; cg = c - 112; }
        else if (c < 208) { k = 5; wp = w25; cg = c - 160; }
        else              { k = 7; wp = w27; cg = c - 208; }
        float wr[7];
#pragma unroll
        for (int q = 0; q < 7; q++) wr[q] = (q < k) ? __ldg(&wp[cg * k + q]) : 0.0f;
        int pad = (k - 1) >> 1;
#pragma unroll
        for (int t = 0; t < 8; t++) {
            float sum = 0.0f;
#pragma unroll
            for (int q = 0; q < 7; q++) {
                int tt = t + q - pad;
                if (q < k && tt >= 0 && tt < 8) sum += wr[q] * v[j][tt];
            }
            o[j][t] = sum;
        }
    }
#pragma unroll
    for (int t = 0; t < 8; t++) {
#pragma unroll
        for (int j = 0; j < 4; j++) s[tx][ty * 4 + j] = o[j][t];
        __syncthreads();
        float* yb = g_y + ((size_t)(n * 8 + t) * HWX + hw0) * CTOT + c0;
#pragma unroll
        for (int j = 0; j < 4; j++)
            yb[(size_t)(ty * 4 + j) * CTOT + tx] = s[ty * 4 + j][tx];
        __syncthreads();
    }
}

// ---------------------------------------------------------------------------
// Winograd input transform: g_y (NHWC fp32) -> V[p][tile][ic] fp16.
// ---------------------------------------------------------------------------
__global__ __launch_bounds__(256) void wino_v_kernel()
{
    const int tid  = threadIdx.x;
    const int tile = blockIdx.x * 2 + (tid >> 7);
    const int icp  = tid & 127;
    const int img  = tile / 784, rem = tile % 784;
    const int tr = rem / 28, tc = rem % 28;
    const int h0 = 2 * tr - 1, w0 = 2 * tc - 1;
    const float* yb = g_y + (size_t)img * HWX * CTOT + icp * 2;

    float ex[4][4], ey[4][4];
#pragma unroll
    for (int c = 0; c < 4; ++c) {
        float dx[4], dy[4];
#pragma unroll
        for (int r = 0; r < 4; ++r) {
            int h = h0 + r, w = w0 + c;
            float2 v = make_float2(0.0f, 0.0f);
            if ((unsigned)h < 56u && (unsigned)w < 56u)
                v = *(const float2*)(yb + (size_t)(h * WW + w) * CTOT);
            dx[r] = v.x; dy[r] = v.y;
        }
        ex[0][c] = dx[0] - dx[2];  ey[0][c] = dy[0] - dy[2];
        ex[1][c] = dx[1] + dx[2];  ey[1][c] = dy[1] + dy[2];
        ex[2][c] = dx[2] - dx[1];  ey[2][c] = dy[2] - dy[1];
        ex[3][c] = dx[1] - dx[3];  ey[3][c] = dy[1] - dy[3];
    }
#pragma unroll
    for (int i = 0; i < 4; ++i) {
        float vx[4], vy[4];
        vx[0] = ex[i][0] - ex[i][2];  vy[0] = ey[i][0] - ey[i][2];
        vx[1] = ex[i][1] + ex[i][2];  vy[1] = ey[i][1] + ey[i][2];
        vx[2] = ex[i][2] - ex[i][1];  vy[2] = ey[i][2] - ey[i][1];
        vx[3] = ex[i][1] - ex[i][3];  vy[3] = ey[i][1] - ey[i][3];
#pragma unroll
        for (int j = 0; j < 4; ++j) {
            *(__half2*)(g_V + ((size_t)(i * 4 + j) * NTILE + tile) * 256 + icp * 2)
                = __floats2half2_rn(vx[j], vy[j]);
        }
    }
}

// ---------------------------------------------------------------------------
// Winograd weight transform: U = G g G^T.
// ---------------------------------------------------------------------------
__global__ void wino_u_kernel(const float* __restrict__ w2d1,
                              const float* __restrict__ w2d2)
{
    int i = blockIdx.x * 256 + threadIdx.x;
    if (i >= 4096 + 36864) return;
    const float* src;
    __half* dst0; int rstride, rowoff;
    if (i < 4096) {
        int oc = i >> 6, ic = i & 63;
        src = w2d1 + (oc * 64 + ic) * 9;
        dst0 = g_UA; rstride = 64 * 64; rowoff = oc * 64 + ic;
    } else {
        int j = i - 4096;
        int oc = j / 192, ic = j % 192;
        src = w2d2 + (oc * 192 + ic) * 9;
        dst0 = g_UB; rstride = 192 * 192; rowoff = oc * 192 + ic;
    }
    float g[3][3];
#pragma unroll
    for (int a = 0; a < 3; ++a)
#pragma unroll
        for (int b = 0; b < 3; ++b) g[a][b] = src[a * 3 + b];
    float u[4][3];
#pragma unroll
    for (int b = 0; b < 3; ++b) {
        u[0][b] = g[0][b];
        u[1][b] = 0.5f * (g[0][b] + g[1][b] + g[2][b]);
        u[2][b] = 0.5f * (g[0][b] - g[1][b] + g[2][b]);
        u[3][b] = g[2][b];
    }
#pragma unroll
    for (int r = 0; r < 4; ++r) {
        float U0 = u[r][0];
        float U1 = 0.5f * (u[r][0] + u[r][1] + u[r][2]);
        float U2 = 0.5f * (u[r][0] - u[r][1] + u[r][2]);
        float U3 = u[r][2];
        dst0[(r * 4 + 0) * rstride + rowoff] = __float2half_rn(U0);
        dst0[(r * 4 + 1) * rstride + rowoff] = __float2half_rn(U1);
        dst0[(r * 4 + 2) * rstride + rowoff] = __float2half_rn(U2);
        dst0[(r * 4 + 3) * rstride + rowoff] = __float2half_rn(U3);
    }
}

// ---------------------------------------------------------------------------
// Winograd GEMM v5: deep staging pipeline.
// CTA = 64 oc x 64 tiles, 8 warps (4 M x 2 N), warp tile 16x32 (R10 numerics).
// K-chunks of 32; 4 buffers of 10 KB; wait_group(2) keeps 2 staging chunks
// in flight; 1 __syncthreads per chunk; shift/mask staging (1 A + 1 B op/thr).
// ---------------------------------------------------------------------------
#define KH    32
#define ST    80u                    // row stride bytes (32 halves + 16 pad)
#define BOFF  (64u * ST)             // 5120
#define BUFSZ (128u * ST)            // 10240
#define SMEM_BYTES (4u * BUFSZ)      // 40960

#define LDSM_X4(r0, r1, r2, r3, addr) \
    asm volatile("ldmatrix.sync.aligned.m8n8.x4.shared.b16 {%0,%1,%2,%3}, [%4];" \
        : "=r"(r0), "=r"(r1), "=r"(r2), "=r"(r3) : "r"(addr))

template<bool ISA>
__device__ __forceinline__ void wino_body(float* __restrict__ out,
                                          const __half* __restrict__ smbase)
{
    constexpr int ICN  = ISA ? 64 : 192;
    constexpr int NCHP = ICN / KH;          // chunks per position: 2 / 6
    constexpr int NCH  = 16 * NCHP;         // 32 / 96
    constexpr size_t APS = (size_t)ICN * (ISA ? 64 : 192);
    constexpr size_t BPS = (size_t)NTILE * 256;

    const uint32_t smb = smem_u32(smbase);
    const int tid = threadIdx.x, wid = tid >> 5, lane = tid & 31;
    const int octile = blockIdx.x;
    const int n0 = blockIdx.y * 64;

    const __half* Ab = ISA ? g_UA : g_UB + (size_t)((octile - 1) * 64) * 192;
    const __half* Bb = g_V + (size_t)n0 * 256 + (ISA ? 0 : 64);

    // shift/mask staging coords: 128 rows total (64 A + 64 B), 4 chunks each
    const int row = tid >> 2, kq = tid & 3;
    const uint32_t dA = smb + row * ST + kq * 16;
    const uint32_t dB = dA + BOFF;
    const size_t offA = (size_t)row * ICN + kq * 8;
    const size_t offB = (size_t)row * 256 + kq * 8;

    auto stage = [&](int c) {
        const int p = c / NCHP, q = c - (c / NCHP) * NCHP;   // constexpr divisor
        const uint32_t bb = (uint32_t)(c & 3) * BUFSZ;
        const __half* As = Ab + (size_t)p * APS + q * KH + offA;
        const __half* Bs = Bb + (size_t)p * BPS + q * KH + offB;
        asm volatile("cp.async.cg.shared.global [%0], [%1], 16;"
                     :: "r"(dA + bb), "l"(As));
        asm volatile("cp.async.cg.shared.global [%0], [%1], 16;"
                     :: "r"(dB + bb), "l"(Bs));
        asm volatile("cp.async.commit_group;" ::: "memory");
    };

    float Z[4][4][4];
#pragma unroll
    for (int a = 0; a < 4; ++a)
#pragma unroll
        for (int b = 0; b < 4; ++b)
#pragma unroll
            for (int c = 0; c < 4; ++c) Z[a][b][c] = 0.0f;

    float M[4][4];
    const int wm = wid & 3, wn = wid >> 2;
    const int l15 = lane & 15;
    const int kh16 = (lane >> 4) * 16;
    const uint32_t aAo = (wm * 16 + l15) * ST + kh16;
    const uint32_t aBo = BOFF + (wn * 32 + l15) * ST + kh16;

    stage(0); stage(1); stage(2);

    for (int c = 0; c < NCH; ++c) {
        // wait so that group c is complete (outstanding = {c..min(c+2,NCH-1)})
        if (c + 2 < NCH)
            asm volatile("cp.async.wait_group 2;" ::: "memory");
        else if (c + 1 < NCH)
            asm volatile("cp.async.wait_group 1;" ::: "memory");
        else
            asm volatile("cp.async.wait_group 0;" ::: "memory");
        __syncthreads();            // all warps done with chunk c-1; buf c ready
        if (c + 3 < NCH) stage(c + 3);

        const int q = c - (c / NCHP) * NCHP;
        if (q == 0) {
#pragma unroll
            for (int a = 0; a < 4; ++a)
#pragma unroll
                for (int b = 0; b < 4; ++b) M[a][b] = 0.0f;
        }

        const uint32_t bb = smb + (uint32_t)(c & 3) * BUFSZ;
        const uint32_t aA = bb + aAo;
        const uint32_t aB = bb + aBo;

#pragma unroll
        for (int ks = 0; ks < 2; ++ks) {       // KH=32 -> 2 K16 steps
            uint32_t a[4], b[4][2];
            LDSM_X4(a[0], a[1], a[2], a[3], aA + ks * 32);
            LDSM_X4(b[0][0], b[1][0], b[0][1], b[1][1], aB + ks * 32);
            LDSM_X4(b[2][0], b[3][0], b[2][1], b[3][1], aB + 16 * ST + ks * 32);
#pragma unroll
            for (int nt = 0; nt < 4; ++nt)
                asm volatile(
                    "mma.sync.aligned.m16n8k16.row.col.f32.f16.f16.f32 "
                    "{%0,%1,%2,%3}, {%4,%5,%6,%7}, {%8,%9}, {%0,%1,%2,%3};"
                    : "+f"(M[nt][0]), "+f"(M[nt][1]),
                      "+f"(M[nt][2]), "+f"(M[nt][3])
                    : "r"(a[0]), "r"(a[1]), "r"(a[2]), "r"(a[3]),
                      "r"(b[nt][0]), "r"(b[nt][1]));
        }

        if (q == NCHP - 1) {
            // inverse-transform fold: At = [[1,1,1,0],[0,1,-1,-1]]
            const int p = c / NCHP;
            int pi = p >> 2, pj = p & 3;
            float fi0 = (pi < 3) ? 1.0f : 0.0f;
            float fi1 = (pi == 0) ? 0.0f : ((pi == 1) ? 1.0f : -1.0f);
            float fj0 = (pj < 3) ? 1.0f : 0.0f;
            float fj1 = (pj == 0) ? 0.0f : ((pj == 1) ? 1.0f : -1.0f);
            float c00 = fi0 * fj0, c01 = fi0 * fj1, c10 = fi1 * fj0, c11 = fi1 * fj1;
#pragma unroll
            for (int nt = 0; nt < 4; ++nt)
#pragma unroll
                for (int e = 0; e < 4; ++e) {
                    float m = M[nt][e];
                    Z[nt][e][0] += c00 * m;
                    Z[nt][e][1] += c01 * m;
                    Z[nt][e][2] += c10 * m;
                    Z[nt][e][3] += c11 * m;
                }
        }
    }

    // Epilogue: Z -> out NCHW fp32.
    const int g = lane >> 2, t4 = lane & 3;
    const int oc0 = octile * 64 + wm * 16 + g;
#pragma unroll
    for (int nt = 0; nt < 4; ++nt) {
        int tl0 = n0 + wn * 32 + nt * 8 + 2 * t4;
#pragma unroll
        for (int et = 0; et < 2; ++et) {
            int tile = tl0 + et;
            int img = tile / 784, rem = tile % 784;
            int tr = rem / 28, tc = rem % 28;
            size_t obase = ((size_t)img * CTOT + oc0) * HWX + (2 * tr) * WW + 2 * tc;
#pragma unroll
            for (int er = 0; er < 2; ++er) {
                int e = er * 2 + et;
                size_t ob = obase + (size_t)er * 8 * HWX;
                *(float2*)(out + ob)      = make_float2(Z[nt][e][0], Z[nt][e][1]);
                *(float2*)(out + ob + WW) = make_float2(Z[nt][e][2], Z[nt][e][3]);
            }
        }
    }
}

__global__ __launch_bounds__(256, 2) void wino_gemm_kernel(float* __restrict__ out)
{
    extern __shared__ __half smh[];
    if (blockIdx.x == 0) wino_body<true>(out, smh);
    else                 wino_body<false>(out, smh);
}

// ---------------------------------------------------------------------------
// Inputs: x, w11, w13, w15, w17, w21, w23, w25, w27, w2d1, w2d2, n_segment
// ---------------------------------------------------------------------------
extern "C" void kernel_launch(void* const* d_in, const int* in_sizes, int n_in,
                              void* d_out, int out_size)
{
    const float* x    = (const float*)d_in[0];
    const float* w11  = (const float*)d_in[1];
    const float* w13  = (const float*)d_in[2];
    const float* w15  = (const float*)d_in[3];
    const float* w17  = (const float*)d_in[4];
    const float* w21  = (const float*)d_in[5];
    const float* w23  = (const float*)d_in[6];
    const float* w25  = (const float*)d_in[7];
    const float* w27  = (const float*)d_in[8];
    const float* w2d1 = (const float*)d_in[9];
    const float* w2d2 = (const float*)d_in[10];
    float* out = (float*)d_out;

    cudaFuncSetAttribute(wino_gemm_kernel,
                         cudaFuncAttributeMaxDynamicSharedMemorySize, SMEM_BYTES);

    dim3 g1(98, 8, 8), b1(32, 8);
    temporal_nhwc_kernel<<<g1, b1>>>(x, w11, w13, w15, w17, w21, w23, w25, w27);
    wino_u_kernel<<<160, 256>>>(w2d1, w2d2);
    wino_v_kernel<<<NTILE / 2, 256>>>();
    wino_gemm_kernel<<<dim3(4, 784), 256, SMEM_BYTES>>>(out);
}